// round 17
// baseline (speedup 1.0000x reference)
#include <cuda_runtime.h>
#include <cuda_fp16.h>
#include <math.h>
#include <cstdint>

// Problem constants
#define TT 4096
#define CC 1024
#define HH 16
#define DD 64
// Q scale folded with log2(e): scores come out in log2 domain -> P = 2^s
#define QSC 0.18033688f   // 0.125 * 1.44269504

// Scratch (allocation-free: __device__ globals). All fp16 fragment-major.
__device__ uint4 g_q[524288];      // 8 MB: Q fp16 A-frag  [qt][h][ks][lane]
__device__ uint4 g_xfrag[524288];  // 8 MB: x fp16 A-frag  [by][kc][mt][ks][lane]
__device__ uint4 g_khalf[524288];  // 8 MB: K fp16 B-frag  [h][jt][ks][n8p][lane]
__device__ uint4 g_vhalf[524288];  // 8 MB: V fp16 B-frag  [h][jt][kb][n8p][lane]
__device__ uint4 g_attnf[524288];  // 8 MB: attn out fp16 A-frag (GEMM2 input)
__device__ uint4 g_wpa[393216];    // 6 MB: W_attn fp16 B-frag [kc][n8pg][ks][lane]
__device__ uint4 g_wpp[131072];    // 2 MB: W_proj fp16 B-frag

// ---------------------------------------------------------------------------
// PTX helpers
// ---------------------------------------------------------------------------
__device__ __forceinline__ uint16_t f16b(float f) {
    uint16_t u;
    asm("cvt.rn.f16.f32 %0, %1;" : "=h"(u) : "f"(f));
    return u;
}
__device__ __forceinline__ uint32_t packf16(float hi, float lo) {
    uint32_t u;
    asm("cvt.rn.f16x2.f32 %0, %1, %2;" : "=r"(u) : "f"(hi), "f"(lo));
    return u;
}
__device__ __forceinline__ uint32_t ex2h2(uint32_t x) {
    uint32_t r;
    asm("ex2.approx.f16x2 %0, %1;" : "=r"(r) : "r"(x));
    return r;
}
// fp32-accumulate fp16 mma
__device__ __forceinline__ void mma16(float* c, const uint32_t* a, uint32_t b0, uint32_t b1) {
    asm volatile(
        "mma.sync.aligned.m16n8k16.row.col.f32.f16.f16.f32 "
        "{%0,%1,%2,%3}, {%4,%5,%6,%7}, {%8,%9}, {%0,%1,%2,%3};"
        : "+f"(c[0]), "+f"(c[1]), "+f"(c[2]), "+f"(c[3])
        : "r"(a[0]), "r"(a[1]), "r"(a[2]), "r"(a[3]), "r"(b0), "r"(b1));
}
// fp16-accumulate fp16 mma: D (2x b32 = 4 halves) — used for QK scores.
//  d0 = (row gid, col 2tig | 2tig+1), d1 = (row gid+8, same cols)
__device__ __forceinline__ void mma16h(uint32_t* d, const uint32_t* a, uint32_t b0, uint32_t b1) {
    asm volatile(
        "mma.sync.aligned.m16n8k16.row.col.f16.f16.f16.f16 "
        "{%0,%1}, {%2,%3,%4,%5}, {%6,%7}, {%0,%1};"
        : "+r"(d[0]), "+r"(d[1])
        : "r"(a[0]), "r"(a[1]), "r"(a[2]), "r"(a[3]), "r"(b0), "r"(b1));
}
__device__ __forceinline__ uint32_t smem_u32(const void* p) {
    uint32_t a;
    asm("{ .reg .u64 t; cvta.to.shared.u64 t, %1; cvt.u32.u64 %0, t; }" : "=r"(a) : "l"(p));
    return a;
}
__device__ __forceinline__ void cpa16(uint32_t s, const void* g) {
    asm volatile("cp.async.cg.shared.global [%0], [%1], 16;" :: "r"(s), "l"(g));
}
#define CP_COMMIT() asm volatile("cp.async.commit_group;" ::: "memory")
#define CP_WAIT2()  asm volatile("cp.async.wait_group 2;" ::: "memory")
#define ONES_H2 0x3C003C00u   // fp16x2 (1.0, 1.0)
#define MASKH   0xFBFFu       // fp16 -65504 ; ex2 -> 0
#define MASKH2  0xFBFFFBFFu

// fp16 m16n8k16 fragments (lane = gid*4 + tig):
//  A(16x16): a0=(gid, 2tig|2tig+1) a1=(gid+8, same) a2=(gid, 2tig+8|+9) a3=(gid+8, ..)
//  B(16x8 col): b0=(k=2tig|2tig+1, n=gid)  b1=(k=2tig+8|+9, n=gid)
//  C f32(16x8): c0=(gid,2tig) c1=(gid,2tig+1) c2=(gid+8,2tig) c3=(gid+8,2tig+1)
//  C f16(16x8): d0 = packed (gid, 2tig|2tig+1), d1 = packed (gid+8, ...)
//  f16 QK C-frag regs ARE the PV A-frag regs (post-ex2): zero packs, zero shuffles.
//
// A-frag chunk (128x32): [mt(8)][ks(2)][lane(32)] uint4 = 512 u4 = 8KB
// B-frag chunk (32x128): [n8p(8)][ks(2)][lane] uint4
// K tile (64x64): [ks(4)][n8p(4)][lane] = 512 u4 = 8KB;  V tile same.
// Pipeline: 3 stages x 2 chunks/tiles per stage (32KB/stage, 96KB total).

// ---------------------------------------------------------------------------
// Prepack x -> fp16 A-frag. One uint4 per thread.
// ---------------------------------------------------------------------------
__global__ __launch_bounds__(256) void prepack_a(
    const float* __restrict__ X, uint4* __restrict__ Af)
{
    int fid = blockIdx.x * 256 + threadIdx.x;
    int lane = fid & 31;
    int ks = (fid >> 5) & 1;
    int mt = (fid >> 6) & 7;
    int kc = (fid >> 9) & 31;
    int by = fid >> 14;
    int gid = lane >> 2, tig = lane & 3;
    int r0 = by * 128 + mt * 16 + gid;
    int c0 = kc * 32 + ks * 16 + 2 * tig;
    const float* x0 = X + (size_t)r0 * 1024 + c0;
    float2 p00 = *(const float2*)x0;
    float2 p10 = *(const float2*)(x0 + 8 * 1024);
    float2 p08 = *(const float2*)(x0 + 8);
    float2 p18 = *(const float2*)(x0 + 8 * 1024 + 8);
    uint4 v;
    v.x = packf16(p00.y, p00.x);
    v.y = packf16(p10.y, p10.x);
    v.z = packf16(p08.y, p08.x);
    v.w = packf16(p18.y, p18.x);
    Af[fid] = v;
}

// ---------------------------------------------------------------------------
// Weight prepack: W[K][N] row-major -> fp16 B-frag [kc][n8pg][ks][lane]
// ---------------------------------------------------------------------------
__global__ __launch_bounds__(256) void prepack_w(
    const float* __restrict__ W, uint4* __restrict__ Wp, int N)
{
    __shared__ float tile[32][65];
    const int tid = threadIdx.x;
    const int nb = blockIdx.x * 64, kb = blockIdx.y * 32;

    #pragma unroll
    for (int p = 0; p < 2; p++) {
        int row = p * 16 + (tid >> 4);
        int col = (tid & 15) * 4;
        float4 v = *(const float4*)(W + (size_t)(kb + row) * N + nb + col);
        tile[row][col + 0] = v.x; tile[row][col + 1] = v.y;
        tile[row][col + 2] = v.z; tile[row][col + 3] = v.w;
    }
    __syncthreads();

    const int n8pl = tid >> 6;
    const int ks = (tid >> 5) & 1;
    const int lane = tid & 31;
    const int gid = lane >> 2, tigb = lane & 3;
    const int kr = ks * 16 + 2 * tigb;
    const int ne = n8pl * 16 + gid, no = ne + 8;
    uint4 v;
    v.x = packf16(tile[kr + 1][ne], tile[kr][ne]);
    v.y = packf16(tile[kr + 9][ne], tile[kr + 8][ne]);
    v.z = packf16(tile[kr + 1][no], tile[kr][no]);
    v.w = packf16(tile[kr + 9][no], tile[kr + 8][no]);
    Wp[((size_t)(kb >> 5) * (N >> 4) + (nb >> 4) + n8pl) * 64 + ks * 32 + lane] = v;
}

// ---------------------------------------------------------------------------
// fp16 mma GEMM (fp32 acc), fully prepacked, 3-stage x double-chunk pipeline.
// Block 128x128, 256 threads (8 warps, 4m x 2n). Stage 32KB, smem 96KB.
// mode 0: fp32 row-major out. mode 1 (QKV): Q/K/V fp16 frag split.
// ---------------------------------------------------------------------------
__global__ __launch_bounds__(256, 2) void gemm_f16(
    const uint4* __restrict__ Af, const uint4* __restrict__ Wp,
    const float* __restrict__ bias, float* __restrict__ Cmat,
    int M, int N, int K, int mode,
    uint4* __restrict__ qf, uint4* __restrict__ kf, uint16_t* __restrict__ vh)
{
    extern __shared__ __align__(16) uint4 smu[];   // 3 * 2048 uint4

    const int tid = threadIdx.x;
    const int lane = tid & 31, wid = tid >> 5;
    const int wm = wid & 3, wn = wid >> 2;
    const int bx = blockIdx.x, by = blockIdx.y;
    const int NC = K >> 5;
    const int NST = NC >> 1;

    const uint32_t smb = smem_u32(smu);

    float acc[2][8][4];
    #pragma unroll
    for (int i = 0; i < 2; i++)
        #pragma unroll
        for (int j = 0; j < 8; j++)
            #pragma unroll
            for (int e = 0; e < 4; e++) acc[i][j][e] = 0.f;

    auto issue = [&](int st) {
        uint32_t dst = smb + (uint32_t)(st % 3) * 32768u;
        const uint4* as = Af + ((size_t)by * NC + 2 * st) * 512;
        #pragma unroll
        for (int i = 0; i < 4; i++)
            cpa16(dst + (tid + 256 * i) * 16, as + tid + 256 * i);
        #pragma unroll
        for (int hh = 0; hh < 2; hh++) {
            const uint4* bs = Wp + ((size_t)(2 * st + hh) * (N >> 4) + bx * 8) * 64;
            cpa16(dst + 16384 + hh * 8192 + tid * 16, bs + tid);
            cpa16(dst + 16384 + hh * 8192 + (tid + 256) * 16, bs + tid + 256);
        }
    };

    issue(0); CP_COMMIT();
    issue(1); CP_COMMIT();
    issue(2); CP_COMMIT();

    for (int st = 0; st < NST; st++) {
        CP_WAIT2();
        __syncthreads();
        const uint4* stage = smu + (st % 3) * 2048;

        #pragma unroll
        for (int hh = 0; hh < 2; hh++) {
            const uint4* sA = stage + hh * 512;
            const uint4* sB = stage + 1024 + hh * 512;
            #pragma unroll
            for (int ks = 0; ks < 2; ks++) {
                uint4 a0v = sA[((2 * wm) * 2 + ks) * 32 + lane];
                uint4 a1v = sA[((2 * wm + 1) * 2 + ks) * 32 + lane];
                #pragma unroll
                for (int n8p = 0; n8p < 4; n8p++) {
                    uint4 bb = sB[((wn * 4 + n8p) * 2 + ks) * 32 + lane];
                    mma16(acc[0][2 * n8p],     (const uint32_t*)&a0v, bb.x, bb.y);
                    mma16(acc[1][2 * n8p],     (const uint32_t*)&a1v, bb.x, bb.y);
                    mma16(acc[0][2 * n8p + 1], (const uint32_t*)&a0v, bb.z, bb.w);
                    mma16(acc[1][2 * n8p + 1], (const uint32_t*)&a1v, bb.z, bb.w);
                }
            }
        }

        __syncthreads();
        if (st + 3 < NST) issue(st + 3);
        CP_COMMIT();
    }

    // ---- Epilogue ----
    const int gid = lane >> 2, tig = lane & 3;

    if (mode == 0) {
        #pragma unroll
        for (int mt2 = 0; mt2 < 2; mt2++) {
            int row0 = by * 128 + wm * 32 + mt2 * 16 + gid;
            #pragma unroll
            for (int nt = 0; nt < 8; nt++) {
                int col = bx * 128 + wn * 64 + nt * 8 + tig * 2;
                float2 bs = *(const float2*)(bias + col);
                float2 v0, v1;
                v0.x = acc[mt2][nt][0] + bs.x;
                v0.y = acc[mt2][nt][1] + bs.y;
                v1.x = acc[mt2][nt][2] + bs.x;
                v1.y = acc[mt2][nt][3] + bs.y;
                *(float2*)(Cmat + (size_t)row0 * N + col) = v0;
                *(float2*)(Cmat + (size_t)(row0 + 8) * N + col) = v1;
            }
        }
    } else if (bx < 8) {
        // Q: fp16 A-frag [qt][h][ks][lane], scaled by SCALE*log2e (log2-domain QK)
        #pragma unroll
        for (int mt2 = 0; mt2 < 2; mt2++) {
            int row = by * 128 + wm * 32 + mt2 * 16 + gid;
            int qt = row >> 4;
            #pragma unroll
            for (int nt = 0; nt < 8; nt++) {
                int d = bx * 128 + wn * 64 + nt * 8 + tig * 2;
                float2 bs = *(const float2*)(bias + d);
                float c0 = (acc[mt2][nt][0] + bs.x) * QSC;
                float c1 = (acc[mt2][nt][1] + bs.y) * QSC;
                float c2 = (acc[mt2][nt][2] + bs.x) * QSC;
                float c3 = (acc[mt2][nt][3] + bs.y) * QSC;
                int h = d >> 6, dl = d & 63;
                int ks = dl >> 4, u = (dl >> 3) & 1;
                uint32_t* qb = (uint32_t*)(qf + (((size_t)qt * 16 + h) * 4 + ks) * 32 + lane);
                qb[2 * u]     = packf16(c1, c0);
                qb[2 * u + 1] = packf16(c3, c2);
            }
        }
    } else if (bx < 16) {
        // K: fp16 B-frag [h][jt][ks][n8p][lane]
        #pragma unroll
        for (int mt2 = 0; mt2 < 2; mt2++) {
            int row = by * 128 + wm * 32 + mt2 * 16 + gid;   // j global
            int jt = row >> 6, jl = row & 63;
            #pragma unroll
            for (int nt = 0; nt < 8; nt++) {
                int colg = bx * 128 + wn * 64 + nt * 8 + tig * 2;
                float2 bs = *(const float2*)(bias + colg);
                float c0 = acc[mt2][nt][0] + bs.x;
                float c1 = acc[mt2][nt][1] + bs.y;
                float c2 = acc[mt2][nt][2] + bs.x;
                float c3 = acc[mt2][nt][3] + bs.y;
                int colk = colg - 1024;
                int h = colk >> 6, d = colk & 63;
                int ks = d >> 4, breg = (d >> 3) & 1;
                int n80 = jl >> 3, n81 = (jl + 8) >> 3;
                uint32_t* tb = (uint32_t*)(kf + (size_t)(h * 64 + jt) * 512);
                uint32_t i0 = ((ks * 4 + (n80 >> 1)) * 32 + lane) * 4 + (n80 & 1) * 2 + breg;
                uint32_t i1 = ((ks * 4 + (n81 >> 1)) * 32 + lane) * 4 + (n81 & 1) * 2 + breg;
                tb[i0] = packf16(c1, c0);
                tb[i1] = packf16(c3, c2);
            }
        }
    } else {
        // V: fp16 B-frag (k = j)
        #pragma unroll
        for (int mt2 = 0; mt2 < 2; mt2++) {
            int row = by * 128 + wm * 32 + mt2 * 16 + gid;   // j global
            int jt = row >> 6, jl = row & 63;
            int kb = jl >> 4;
            int tb = (jl & 7) >> 1;
            int e  = jl & 1;
            #pragma unroll
            for (int nt = 0; nt < 8; nt++) {
                int colg = bx * 128 + wn * 64 + nt * 8 + tig * 2;
                float2 bs = *(const float2*)(bias + colg);
                int colv = colg - 2048;
                int h = colv >> 6, d = colv & 63;     // d even
                int n8 = d >> 3, n8p = n8 >> 1, odd = n8 & 1;
                int lane0 = (d & 7) * 4 + tb;
                size_t tbase = (size_t)(h * 64 + jt) * 4096;   // halves per tile
                size_t i00 = tbase + (size_t)((((kb * 4 + n8p) * 32 + lane0) * 2 + odd) * 2 + 0) * 2 + e;
                size_t i10 = i00 + 32;   // lane0+4 (d+1)
                vh[i00]     = f16b(acc[mt2][nt][0] + bs.x);
                vh[i10]     = f16b(acc[mt2][nt][1] + bs.y);
                vh[i00 + 2] = f16b(acc[mt2][nt][2] + bs.x);
                vh[i10 + 2] = f16b(acc[mt2][nt][3] + bs.y);
            }
        }
    }
}

// ---------------------------------------------------------------------------
// Causal flash attention: QK fp16-acc mma (scores land packed), P = ex2(f16x2),
// l = P@ones (fp32 mma), PV fp32-acc mma. 3-stage x 2-tile cp.async pipeline.
// ---------------------------------------------------------------------------
__global__ __launch_bounds__(256, 2) void attn_mma(
    const uint4* __restrict__ gq, const uint4* __restrict__ khalf,
    const uint4* __restrict__ vhalf, uint4* __restrict__ outf)
{
    extern __shared__ __align__(16) uint4 smu[];   // 3 * 2048 uint4

    const int tid = threadIdx.x;
    const int lane = tid & 31, wid = tid >> 5;
    const int gid = lane >> 2, tig = lane & 3;
    const int h = blockIdx.y;
    const int qb0 = (gridDim.x - 1 - (int)blockIdx.x) * 128;   // heavy blocks first
    const int qr0 = qb0 + wid * 16;
    const int nt = qb0 / 64 + 2;
    const int NST = (nt + 1) >> 1;

    const uint32_t smb = smem_u32(smu);
    const uint4* ksrc = khalf + (size_t)(h * 64) * 512;
    const uint4* vsrc = vhalf + (size_t)(h * 64) * 512;

    // Resident Q A-frags (fp16, pre-scaled into log2 domain by GEMM1)
    uint4 qa[4];
    {
        const int qt = qr0 >> 4;
        #pragma unroll
        for (int ks = 0; ks < 4; ks++)
            qa[ks] = gq[(((size_t)qt * 16 + h) * 4 + ks) * 32 + lane];
    }

    float o[8][4];
    #pragma unroll
    for (int i = 0; i < 8; i++)
        #pragma unroll
        for (int e = 0; e < 4; e++) o[i][e] = 0.f;
    float lacc[4] = {0.f, 0.f, 0.f, 0.f};

    auto issue = [&](int s) {
        uint32_t dst0 = smb + (uint32_t)(s % 3) * 32768u;
        #pragma unroll
        for (int hh = 0; hh < 2; hh++) {
            int tl = 2 * s + hh;
            if (tl < nt) {
                uint32_t dst = dst0 + hh * 16384u;
                const uint4* ks = ksrc + (size_t)tl * 512;
                const uint4* vs = vsrc + (size_t)tl * 512;
                cpa16(dst + tid * 16, ks + tid);
                cpa16(dst + (tid + 256) * 16, ks + tid + 256);
                cpa16(dst + 8192 + tid * 16, vs + tid);
                cpa16(dst + 8192 + (tid + 256) * 16, vs + tid + 256);
            }
        }
    };

    #pragma unroll
    for (int p = 0; p < 3; p++) {
        if (p < NST) issue(p);
        CP_COMMIT();
    }

    for (int s = 0; s < NST; s++) {
        CP_WAIT2();
        __syncthreads();
        const uint4* stage = smu + (s % 3) * 2048;

        #pragma unroll
        for (int hh = 0; hh < 2; hh++) {
            const int tl = 2 * s + hh;
            const int j0 = tl * 64;
            if (tl < nt && j0 <= qr0 + 15) {
                const uint4* sK = stage + hh * 1024;
                const uint4* sV = sK + 512;

                // ---- S = Q K^T (fp16-acc mma: scores land packed) ----
                // sc16[n8] = {d0: rows gid, d1: rows gid+8}, cols j0+8n8+2tig|+1
                uint32_t sc16[8][2];
                #pragma unroll
                for (int i = 0; i < 8; i++) { sc16[i][0] = 0u; sc16[i][1] = 0u; }
                #pragma unroll
                for (int ks = 0; ks < 4; ks++) {
                    #pragma unroll
                    for (int n8p = 0; n8p < 4; n8p++) {
                        uint4 bb = sK[(ks * 4 + n8p) * 32 + lane];
                        mma16h(sc16[2 * n8p],     (const uint32_t*)&qa[ks], bb.x, bb.y);
                        mma16h(sc16[2 * n8p + 1], (const uint32_t*)&qa[ks], bb.z, bb.w);
                    }
                }

                // ---- causal mask (packed halves; MASKH -> ex2 -> 0) ----
                if (j0 + 63 > qr0) {
                    const int rg0 = qr0 + gid, rg1 = rg0 + 8;
                    #pragma unroll
                    for (int n8 = 0; n8 < 8; n8++) {
                        int jg = j0 + n8 * 8 + tig * 2;
                        if (jg > rg0)          sc16[n8][0] = MASKH2;
                        else if (jg + 1 > rg0) sc16[n8][0] = (sc16[n8][0] & 0xFFFFu) | (MASKH << 16);
                        if (jg > rg1)          sc16[n8][1] = MASKH2;
                        else if (jg + 1 > rg1) sc16[n8][1] = (sc16[n8][1] & 0xFFFFu) | (MASKH << 16);
                    }
                }

                // ---- P = 2^s ; l += P@1 ; O += P V (QK C-regs ARE PV A-regs) ----
                #pragma unroll
                for (int kb = 0; kb < 4; kb++) {
                    uint32_t pa[4];
                    pa[0] = ex2h2(sc16[2 * kb][0]);
                    pa[1] = ex2h2(sc16[2 * kb][1]);
                    pa[2] = ex2h2(sc16[2 * kb + 1][0]);
                    pa[3] = ex2h2(sc16[2 * kb + 1][1]);
                    mma16(lacc, pa, ONES_H2, ONES_H2);
                    #pragma unroll
                    for (int n8p = 0; n8p < 4; n8p++) {
                        uint4 vv = sV[(kb * 4 + n8p) * 32 + lane];
                        mma16(o[2 * n8p],     pa, vv.x, vv.y);
                        mma16(o[2 * n8p + 1], pa, vv.z, vv.w);
                    }
                }
            }
        }

        __syncthreads();
        if (s + 3 < NST) issue(s + 3);
        CP_COMMIT();
    }

    // ---- finalize: l exact per-row (ones-mma) + fp16 A-frag store ----
    const float inv0 = 1.f / lacc[0], inv1 = 1.f / lacc[2];
    const int by = qr0 >> 7;
    const int mt = wid;
    #pragma unroll
    for (int n8 = 0; n8 < 8; n8++) {
        int c0 = h * 64 + n8 * 8 + 2 * tig;
        int kc = c0 >> 5;
        int ks = (c0 >> 4) & 1;
        int u = (c0 >> 3) & 1;
        uint32_t* ab = (uint32_t*)(outf + ((((size_t)by * 32 + kc) * 8 + mt) * 2 + ks) * 32 + lane);
        ab[2 * u]     = packf16(o[n8][1] * inv0, o[n8][0] * inv0);
        ab[2 * u + 1] = packf16(o[n8][3] * inv1, o[n8][2] * inv1);
    }
}

// ---------------------------------------------------------------------------
// Launch
// ---------------------------------------------------------------------------
extern "C" void kernel_launch(void* const* d_in, const int* in_sizes, int n_in,
                              void* d_out, int out_size)
{
    const float* x      = (const float*)d_in[0];
    const float* W_attn = (const float*)d_in[1];
    const float* b_attn = (const float*)d_in[2];
    const float* W_proj = (const float*)d_in[3];
    const float* b_proj = (const float*)d_in[4];
    float* out = (float*)d_out;

    uint4 *gq = nullptr, *xfr = nullptr, *kfr = nullptr, *vfr = nullptr;
    uint4 *attn = nullptr, *wpa = nullptr, *wpp = nullptr;
    cudaGetSymbolAddress((void**)&gq,   g_q);
    cudaGetSymbolAddress((void**)&xfr,  g_xfrag);
    cudaGetSymbolAddress((void**)&kfr,  g_khalf);
    cudaGetSymbolAddress((void**)&vfr,  g_vhalf);
    cudaGetSymbolAddress((void**)&attn, g_attnf);
    cudaGetSymbolAddress((void**)&wpa,  g_wpa);
    cudaGetSymbolAddress((void**)&wpp,  g_wpp);

    cudaFuncSetAttribute(gemm_f16, cudaFuncAttributeMaxDynamicSharedMemorySize, 98304);
    cudaFuncSetAttribute(attn_mma, cudaFuncAttributeMaxDynamicSharedMemorySize, 98304);

    // Prepacks: x -> fp16 A-frag; weights -> fp16 B-frag
    prepack_a<<<2048, 256>>>(x, xfr);
    prepack_w<<<dim3(3 * CC / 64, CC / 32), 256>>>(W_attn, wpa, 3 * CC);
    prepack_w<<<dim3(CC / 64, CC / 32), 256>>>(W_proj, wpp, CC);

    // GEMM1: QKV projection; epilogue: Q (log2-scaled) / K / V fp16 fragments
    gemm_f16<<<dim3(3 * CC / 128, TT / 128), 256, 98304>>>(
        xfr, wpa, b_attn, nullptr, TT, 3 * CC, CC, 1, gq, kfr, (uint16_t*)vfr);

    // Fused causal flash attention; output fp16 A-frag
    attn_mma<<<dim3(TT / 128, HH), 256, 98304>>>(gq, kfr, vfr, attn);

    // GEMM2: output projection (fp32 row-major epilogue)
    gemm_f16<<<dim3(CC / 128, TT / 128), 256, 98304>>>(
        attn, wpp, b_proj, out, TT, CC, CC, 0, nullptr, nullptr, nullptr);
}